// round 15
// baseline (speedup 1.0000x reference)
#include <cuda_runtime.h>
#include <cuda_bf16.h>
#include <math.h>
#include <stdint.h>

// Problem dims
#define B_   32
#define T_   512
#define IN_  128
#define H_   1024
#define OUT_ 128

// Persistent kernel config
#define NCTA 128
#define NTHR 288                // 8 consumer warps + 1 producer warp

// SMEM layout (bytes)
//   W ring : 4 slots x 32768      [0, 131072)
//   A ring : 2 slots x 32768      [131072, 196608)
//   partials: 8 x 32x33 f32       [196608, 230400)
//   bias   : 64 f32               [230400, 230656)
//   mbars  : WF[4] WE[4] AF[2] AE[2]  [230656, 230752)
#define AR_B  131072
#define PT_B  196608
#define BS_B  230400
#define MB_B  230656
#define SMEM_BYTES 230752

typedef __nv_bfloat16 bf16;

// ---------------------------------------------------------------------------
// Device scratch
// ---------------------------------------------------------------------------
__device__ float d_M0  [4096 * 128];            // Wih0 @ W_emb^T
__device__ float d_bv0 [4096];                  // Wih0 @ b_emb
__device__ float d_G0  [(size_t)T_ * 128 * 32 * 32];   // [t][r][m][b] fp32
__device__ float d_H1  [(size_t)T_ * B_ * H_];  // layer-1 h, fp32
// Swizzled SMEM-image weight blocks: [(l*128+r)][chunk 0..7][hi 16K][lo 16K]
// l=0: chunks 0..3 = Whh0.  l=1: chunks 0..3 = Wih1, 4..7 = Whh1.
__device__ unsigned char d_Wimg[(size_t)2 * 128 * 8 * 32768];
// Swizzled act images: [parity][chunk 0..3][hi 16K][lo 16K]
__device__ unsigned char d_h0img[2][4 * 32768];
__device__ unsigned char d_h1img[2][4 * 32768];
__device__ unsigned g_arrive;
__device__ unsigned g_release;

// ---------------------------------------------------------------------------
// PTX helpers
// ---------------------------------------------------------------------------
#define NB256() asm volatile("bar.sync 1, 256;" ::: "memory")

__device__ __forceinline__ void bulk_ld(uint32_t dst, const void* src, uint32_t bytes, uint32_t mbar) {
    asm volatile("cp.async.bulk.shared::cta.global.mbarrier::complete_tx::bytes [%0], [%1], %2, [%3];"
                 :: "r"(dst), "l"(src), "r"(bytes), "r"(mbar) : "memory");
}
__device__ __forceinline__ void mbar_init(uint32_t mbar, uint32_t cnt) {
    asm volatile("mbarrier.init.shared.b64 [%0], %1;" :: "r"(mbar), "r"(cnt) : "memory");
}
__device__ __forceinline__ void mbar_expect(uint32_t mbar, uint32_t tx) {
    asm volatile("mbarrier.arrive.expect_tx.shared.b64 _, [%0], %1;" :: "r"(mbar), "r"(tx) : "memory");
}
__device__ __forceinline__ void mbar_arrive(uint32_t mbar) {
    asm volatile("mbarrier.arrive.shared.b64 _, [%0];" :: "r"(mbar) : "memory");
}
__device__ __forceinline__ void mbar_wait(uint32_t mbar, uint32_t ph) {
    asm volatile(
        "{\n\t.reg .pred P;\n\t"
        "WAIT_%=:\n\t"
        "mbarrier.try_wait.parity.shared.b64 P, [%0], %1, 0x989680;\n\t"
        "@P bra.uni DONE_%=;\n\t"
        "bra.uni WAIT_%=;\n\t"
        "DONE_%=:\n\t}"
        :: "r"(mbar), "r"(ph) : "memory");
}
__device__ __forceinline__ void ldsm_x4(uint32_t* r, uint32_t addr) {
    asm volatile("ldmatrix.sync.aligned.m8n8.x4.shared.b16 {%0,%1,%2,%3}, [%4];\n"
                 : "=r"(r[0]), "=r"(r[1]), "=r"(r[2]), "=r"(r[3]) : "r"(addr));
}
__device__ __forceinline__ void mma_bf16(float* c, const uint32_t* a, const uint32_t* b) {
    asm volatile("mma.sync.aligned.m16n8k16.row.col.f32.bf16.bf16.f32 "
                 "{%0,%1,%2,%3}, {%4,%5,%6,%7}, {%8,%9}, {%0,%1,%2,%3};\n"
                 : "+f"(c[0]), "+f"(c[1]), "+f"(c[2]), "+f"(c[3])
                 : "r"(a[0]), "r"(a[1]), "r"(a[2]), "r"(a[3]), "r"(b[0]), "r"(b[1]));
}
__device__ __forceinline__ unsigned ld_acq(const unsigned* p) {
    unsigned v;
    asm volatile("ld.acquire.gpu.global.u32 %0, [%1];" : "=r"(v) : "l"(p));
    return v;
}
// 24 mmas: 3-term bf16-split product of one 32x32 tile slice (one kk)
__device__ __forceinline__ void terms24(float* acc,
    const uint32_t* ah0, const uint32_t* ah1,
    const uint32_t* al0, const uint32_t* al1,
    const uint32_t* bh0, const uint32_t* bh1,
    const uint32_t* bl0, const uint32_t* bl1)
{
    mma_bf16(acc + 0,  ah0, bh0 + 0); mma_bf16(acc + 4,  ah0, bh0 + 2);
    mma_bf16(acc + 8,  ah0, bh1 + 0); mma_bf16(acc + 12, ah0, bh1 + 2);
    mma_bf16(acc + 16, ah1, bh0 + 0); mma_bf16(acc + 20, ah1, bh0 + 2);
    mma_bf16(acc + 24, ah1, bh1 + 0); mma_bf16(acc + 28, ah1, bh1 + 2);

    mma_bf16(acc + 0,  ah0, bl0 + 0); mma_bf16(acc + 4,  ah0, bl0 + 2);
    mma_bf16(acc + 8,  ah0, bl1 + 0); mma_bf16(acc + 12, ah0, bl1 + 2);
    mma_bf16(acc + 16, ah1, bl0 + 0); mma_bf16(acc + 20, ah1, bl0 + 2);
    mma_bf16(acc + 24, ah1, bl1 + 0); mma_bf16(acc + 28, ah1, bl1 + 2);

    mma_bf16(acc + 0,  al0, bh0 + 0); mma_bf16(acc + 4,  al0, bh0 + 2);
    mma_bf16(acc + 8,  al0, bh1 + 0); mma_bf16(acc + 12, al0, bh1 + 2);
    mma_bf16(acc + 16, al1, bh0 + 0); mma_bf16(acc + 20, al1, bh0 + 2);
    mma_bf16(acc + 24, al1, bh1 + 0); mma_bf16(acc + 28, al1, bh1 + 2);
}
// write one activation value into a swizzled chunk-blocked hi/lo image
__device__ __forceinline__ void store_act(unsigned char* img, int b, int u, float v) {
    bf16 hi = __float2bfloat16(v);
    bf16 lo = __float2bfloat16(v - __bfloat162float(hi));
    uint32_t x  = ((uint32_t)(u & 255)) * 2u;
    uint32_t sx = x ^ ((uint32_t)(b & 7) << 4);
    unsigned char* p = img + (((size_t)(u >> 8)) << 15) + (uint32_t)b * 512u + sx;
    unsigned short hb = __bfloat16_as_ushort(hi), lb = __bfloat16_as_ushort(lo);
    asm volatile("st.global.cg.u16 [%0], %1;" :: "l"(p), "h"(hb));
    asm volatile("st.global.cg.u16 [%0], %1;" :: "l"(p + 16384), "h"(lb));
}

// ---------------------------------------------------------------------------
// Full-block grid barrier (init only)
// ---------------------------------------------------------------------------
__device__ __forceinline__ void gridbar_full(unsigned gen) {
    __threadfence();
    __syncthreads();
    if (threadIdx.x == 0) {
        unsigned a = atomicAdd(&g_arrive, 1u) + 1u;
        if (a == (unsigned)NCTA * gen) {
            atomicExch(&g_release, gen);
        } else {
            while (*((volatile unsigned*)&g_release) < gen) __nanosleep(32);
        }
    }
    __syncthreads();
}

// ---------------------------------------------------------------------------
// M0 = Wih0 @ W_emb^T [4096 x 128], bvec0 = Wih0 @ b_emb.  Exact fp32.
// ---------------------------------------------------------------------------
__global__ void m0_kernel(const float* __restrict__ Wih,
                          const float* __restrict__ Wemb,
                          const float* __restrict__ bemb) {
    __shared__ float wih_s[8][1024];
    __shared__ float red[128];
    const int tid = threadIdx.x;
    const int j0  = blockIdx.x * 8;

    if (blockIdx.x == 0 && tid == 0) { g_arrive = 0u; g_release = 0u; }

    for (int i = tid; i < 8 * 1024; i += 128) {
        int jj = i >> 10, k = i & 1023;
        wih_s[jj][k] = Wih[(size_t)(j0 + jj) * 1024 + k];
    }
    __syncthreads();

    float acc[8];
#pragma unroll
    for (int jj = 0; jj < 8; jj++) acc[jj] = 0.f;
    float bp[8];
#pragma unroll
    for (int jj = 0; jj < 8; jj++) bp[jj] = 0.f;

    for (int k = 0; k < 1024; k++) {
        float we = Wemb[k * 128 + tid];
#pragma unroll
        for (int jj = 0; jj < 8; jj++) acc[jj] += wih_s[jj][k] * we;
    }
    for (int k = tid; k < 1024; k += 128) {
        float be = bemb[k];
#pragma unroll
        for (int jj = 0; jj < 8; jj++) bp[jj] += wih_s[jj][k] * be;
    }
#pragma unroll
    for (int jj = 0; jj < 8; jj++) {
        d_M0[(size_t)(j0 + jj) * 128 + tid] = acc[jj];
        __syncthreads();
        red[tid] = bp[jj];
        __syncthreads();
        for (int s = 64; s > 0; s >>= 1) {
            if (tid < s) red[tid] += red[tid + s];
            __syncthreads();
        }
        if (tid == 0) d_bv0[j0 + jj] = red[0];
    }
}

// ---------------------------------------------------------------------------
// G0[t][r][m][b] = x[b][t][:] . M0[j(r,m)][:] + bvec0[j].  grid (128, 512).
// ---------------------------------------------------------------------------
__global__ void g0_kernel(const float* __restrict__ x) {
    __shared__ float xs[32][129];
    const int r = blockIdx.x, t = blockIdx.y;
    const int tid = threadIdx.x;

    for (int i = tid; i < 32 * 128; i += 256) {
        int b = i >> 7, k = i & 127;
        xs[b][k] = x[((size_t)b * T_ + t) * IN_ + k];
    }
    __syncthreads();

    const int m  = tid >> 3;
    const int bq = (tid & 7) * 4;
    const int j  = ((m >> 3) << 10) + (r << 3) + (m & 7);
    const float* M0r = d_M0 + (size_t)j * 128;

    float acc[4];
    const float bv = d_bv0[j];
#pragma unroll
    for (int i = 0; i < 4; i++) acc[i] = bv;

#pragma unroll 4
    for (int k = 0; k < 128; k++) {
        float w = M0r[k];
#pragma unroll
        for (int i = 0; i < 4; i++) acc[i] += w * xs[bq + i][k];
    }
    float4 v = make_float4(acc[0], acc[1], acc[2], acc[3]);
    *(float4*)(d_G0 + (((size_t)t * 128 + r) * 32 + m) * 32 + bq) = v;
}

// ---------------------------------------------------------------------------
// Weight prep (unchanged layout)
// ---------------------------------------------------------------------------
__global__ void prep_weights(const float* __restrict__ Wih,
                             const float* __restrict__ Whh) {
    const int r = blockIdx.x, l = blockIdx.y;
    unsigned char* base = d_Wimg + ((size_t)(l * 128 + r) << 18);

    for (int g = threadIdx.x; g < 8192; g += 256) {
        int c  = g >> 10;
        int m  = (g >> 5) & 31;
        int gk = g & 31;
        if (l == 0 && c >= 4) continue;
        int j = ((m >> 3) << 10) + (r << 3) + (m & 7);
        const float* src;
        if (l == 0)      src = Whh + (size_t)j * 1024 + c * 256 + gk * 8;
        else if (c < 4)  src = Wih + (size_t)(4096 + j) * 1024 + c * 256 + gk * 8;
        else             src = Whh + (size_t)(4096 + j) * 1024 + (c - 4) * 256 + gk * 8;

        float f[8];
        float4 v0 = ((const float4*)src)[0];
        float4 v1 = ((const float4*)src)[1];
        f[0]=v0.x; f[1]=v0.y; f[2]=v0.z; f[3]=v0.w;
        f[4]=v1.x; f[5]=v1.y; f[6]=v1.z; f[7]=v1.w;
        unsigned short hb[8], lb[8];
#pragma unroll
        for (int i = 0; i < 8; i++) {
            bf16 hi = __float2bfloat16(f[i]);
            bf16 lo = __float2bfloat16(f[i] - __bfloat162float(hi));
            hb[i] = __bfloat16_as_ushort(hi);
            lb[i] = __bfloat16_as_ushort(lo);
        }
        uint4 hv, lv;
        hv.x = (uint32_t)hb[0] | ((uint32_t)hb[1] << 16);
        hv.y = (uint32_t)hb[2] | ((uint32_t)hb[3] << 16);
        hv.z = (uint32_t)hb[4] | ((uint32_t)hb[5] << 16);
        hv.w = (uint32_t)hb[6] | ((uint32_t)hb[7] << 16);
        lv.x = (uint32_t)lb[0] | ((uint32_t)lb[1] << 16);
        lv.y = (uint32_t)lb[2] | ((uint32_t)lb[3] << 16);
        lv.z = (uint32_t)lb[4] | ((uint32_t)lb[5] << 16);
        lv.w = (uint32_t)lb[6] | ((uint32_t)lb[7] << 16);
        uint32_t off = (uint32_t)m * 512u + (((uint32_t)gk << 4) ^ ((uint32_t)(m & 7) << 4));
        *(uint4*)(base + ((size_t)c << 15) + off)         = hv;
        *(uint4*)(base + ((size_t)c << 15) + 16384 + off) = lv;
    }
}

// ---------------------------------------------------------------------------
// Output kernel: out[b][t][o] = H1[t][b][:] . W_out[o][:] + b_out
// ---------------------------------------------------------------------------
__global__ void out_kernel(const float* __restrict__ Wout,
                           const float* __restrict__ bout,
                           float* __restrict__ out) {
    __shared__ float hs[B_][128];
    const int t   = blockIdx.x;
    const int tid = threadIdx.x;

    float acc[B_];
    const float bv = bout[tid];
#pragma unroll
    for (int b = 0; b < B_; b++) acc[b] = bv;

    for (int kc = 0; kc < H_; kc += 128) {
        __syncthreads();
        for (int i = tid; i < B_ * 128; i += 128) {
            int b = i >> 7, k = i & 127;
            hs[b][k] = d_H1[((size_t)t * B_ + b) * H_ + kc + k];
        }
        __syncthreads();
        const float4* wr = (const float4*)(Wout + tid * H_ + kc);
#pragma unroll 4
        for (int k4 = 0; k4 < 32; k4++) {
            float4 w = wr[k4];
            int k = k4 * 4;
#pragma unroll
            for (int b = 0; b < B_; b++) {
                acc[b] += hs[b][k] * w.x + hs[b][k + 1] * w.y +
                          hs[b][k + 2] * w.z + hs[b][k + 3] * w.w;
            }
        }
    }
#pragma unroll
    for (int b = 0; b < B_; b++) out[((size_t)b * T_ + t) * OUT_ + tid] = acc[b];
}

// ---------------------------------------------------------------------------
// Persistent LSTM kernel — merged-GEMM schedule with split W/act rings:
//   W ring: 4 x 32 KB slots, act ring: 2 x 32 KB slots, FIFO both sides.
//   prologue: acc0 = Whh0 . h0init -> cell0 -> h0(0)
//   step t:   4 chunks {A=h1(t-1), W=Whh1} -> acc1
//             4 chunks {A=h0(t),  W=Wih1 -> acc1, W=Whh0 -> acc0}
//             cell1 -> h1(t), H1[t];  cell0 (+G0(t+1)) -> h0(t+1), publish
// ---------------------------------------------------------------------------
__global__ void __launch_bounds__(NTHR, 1) lstm_persistent(
    const float* __restrict__ bih, const float* __restrict__ bhh,
    const float* __restrict__ h0)
{
    extern __shared__ char smc[];
    const int tid = threadIdx.x;
    const int r   = blockIdx.x;
    const uint32_t smbase = (uint32_t)__cvta_generic_to_shared(smc);

    if (tid == 0) {
#pragma unroll
        for (int s = 0; s < 4; s++) {
            mbar_init(smbase + MB_B + s * 8, 1);            // W full (tx)
            mbar_init(smbase + MB_B + 32 + s * 8, 8);       // W empty (8 warps)
        }
#pragma unroll
        for (int s = 0; s < 2; s++) {
            mbar_init(smbase + MB_B + 64 + s * 8, 1);       // A full (tx)
            mbar_init(smbase + MB_B + 80 + s * 8, 8);       // A empty (8 warps)
        }
    }
    if (tid < 64) {
        int l = tid >> 5, n = tid & 31;
        int j = ((n >> 3) << 10) + (r << 3) + (n & 7);
        ((float*)(smc + BS_B))[tid] = bih[l * 4 * H_ + j] + bhh[l * 4 * H_ + j];
    }
    float c0 = 0.f, c1 = 0.f;           // register-resident cell state
    if (tid < 256) {
        const int b = tid >> 3, uu = tid & 7;
        const int u = r * 8 + uu;
        const int base = b * (4 * H_);
        float h_l0 = h0[base + 0 * 2 * H_ + u];
        c0         = h0[base + 0 * 2 * H_ + H_ + u];
        float h_l1 = h0[base + 1 * 2 * H_ + u];
        c1         = h0[base + 1 * 2 * H_ + H_ + u];
        store_act(d_h0img[1], b, u, h_l0);   // h0(-1) at parity 1
        store_act(d_h1img[1], b, u, h_l1);   // h1(-1) at parity 1
    }
    gridbar_full(1u);                   // gen 1: init images published

    const unsigned char* wbase0 = d_Wimg + ((size_t)(0 * 128 + r) << 18);
    const unsigned char* wbase1 = d_Wimg + ((size_t)(1 * 128 + r) << 18);

    if (tid >= 256) {
        // ------------------------- PRODUCER (free-running) -------------------
        if (tid == 256) {
            int wq = 0, wiq = 0, wepar = 0;
            int aq = 0, aiq = 0, aepar = 0;
            auto issueW = [&](const unsigned char* src) {
                const int st = wq & 3;
                if (wiq >= 4) {
                    mbar_wait(smbase + MB_B + 32 + st * 8, (uint32_t)((wepar >> st) & 1));
                    wepar ^= (1 << st);
                }
                wiq++;
                uint32_t mb = smbase + MB_B + st * 8;
                mbar_expect(mb, 32768u);
                bulk_ld(smbase + (uint32_t)st * 32768u, src, 32768u, mb);
                wq++;
            };
            auto issueA = [&](const unsigned char* src) {
                const int st = aq & 1;
                if (aiq >= 2) {
                    mbar_wait(smbase + MB_B + 80 + st * 8, (uint32_t)((aepar >> st) & 1));
                    aepar ^= (1 << st);
                }
                aiq++;
                uint32_t mb = smbase + MB_B + 64 + st * 8;
                mbar_expect(mb, 32768u);
                bulk_ld(smbase + AR_B + (uint32_t)st * 32768u, src, 32768u, mb);
                aq++;
            };
            // prologue: Whh0 x h0init (h0img[1])
            for (int c = 0; c < 4; c++) {
                issueA(d_h0img[1] + ((size_t)c << 15));
                issueW(wbase0 + ((size_t)c << 15));
            }
#pragma unroll 1
            for (int t = 0; t < T_; t++) {
                while (ld_acq(&g_release) < (unsigned)(t + 2)) __nanosleep(32);
                // 4 single chunks: Whh1 x h1(t-1) (h1img[(t+1)&1])
                for (int c = 0; c < 4; c++) {
                    issueA(d_h1img[(t + 1) & 1] + ((size_t)c << 15));
                    issueW(wbase1 + ((size_t)(4 + c) << 15));
                }
                // 4 dual chunks: act h0(t) (h0img[t&1]); W = Wih1 then Whh0
                for (int c = 0; c < 4; c++) {
                    issueA(d_h0img[t & 1] + ((size_t)c << 15));
                    issueW(wbase1 + ((size_t)c << 15));
                    issueW(wbase0 + ((size_t)c << 15));
                }
            }
        }
    } else {
        // ------------------------- CONSUMERS ---------------------------------
        const int wid  = tid >> 5;
        const int lane = tid & 31;
        const int jj = lane & 7, s8 = lane >> 3;
        const int cb = (tid >> 3) & 31;
        const int cu = tid & 7;

        const uint32_t rA   = (uint32_t)(((s8 & 1) << 3) + jj);
        const uint32_t dA   = (uint32_t)((s8 >> 1) << 4);
        const uint32_t rB   = (uint32_t)(((s8 >> 1) << 3) + jj);
        const uint32_t dB   = (uint32_t)((s8 & 1) << 4);
        const uint32_t xorJ = (uint32_t)(jj << 4);

        int wq = 0, wparm = 0, aq = 0, aparm = 0;

        float acc0[32], acc1[32];

        // one chunk: act slot + 1 or 2 W slots (shared act ldsm)
        auto chunk = [&](float* accA, float* accB) {
            // acquire act slot
            const int ast = aq & 1;
            mbar_wait(smbase + MB_B + 64 + ast * 8, (uint32_t)((aparm >> ast) & 1));
            aparm ^= (1 << ast);
            const uint32_t bb = smbase + AR_B + (uint32_t)ast * 32768u + rB * 512;
            // acquire W slot(s) in FIFO order
            const int w1 = wq & 3;
            mbar_wait(smbase + MB_B + w1 * 8, (uint32_t)((wparm >> w1) & 1));
            wparm ^= (1 << w1);
            const uint32_t a1 = smbase + (uint32_t)w1 * 32768u + rA * 512;
            int w2 = -1;
            uint32_t a2 = 0;
            if (accB) {
                w2 = (wq + 1) & 3;
                mbar_wait(smbase + MB_B + w2 * 8, (uint32_t)((wparm >> w2) & 1));
                wparm ^= (1 << w2);
                a2 = smbase + (uint32_t)w2 * 32768u + rA * 512;
            }
#pragma unroll
            for (int kx = 0; kx < 2; kx++) {
                const int kk = (wid << 1) + kx;
                const uint32_t offA = (((uint32_t)(kk << 5)) | dA) ^ xorJ;
                const uint32_t offB = (((uint32_t)(kk << 5)) | dB) ^ xorJ;
                uint32_t bh0[4], bh1[4], bl0[4], bl1[4];
                ldsm_x4(bh0, bb + offB);
                ldsm_x4(bh1, bb + 8192 + offB);
                ldsm_x4(bl0, bb + 16384 + offB);
                ldsm_x4(bl1, bb + 16384 + 8192 + offB);
                {
                    uint32_t ah0[4], ah1[4], al0[4], al1[4];
                    ldsm_x4(ah0, a1 + offA);
                    ldsm_x4(ah1, a1 + 8192 + offA);
                    ldsm_x4(al0, a1 + 16384 + offA);
                    ldsm_x4(al1, a1 + 16384 + 8192 + offA);
                    terms24(accA, ah0, ah1, al0, al1, bh0, bh1, bl0, bl1);
                }
                if (accB) {
                    uint32_t ah0[4], ah1[4], al0[4], al1[4];
                    ldsm_x4(ah0, a2 + offA);
                    ldsm_x4(ah1, a2 + 8192 + offA);
                    ldsm_x4(al0, a2 + 16384 + offA);
                    ldsm_x4(al1, a2 + 16384 + 8192 + offA);
                    terms24(accB, ah0, ah1, al0, al1, bh0, bh1, bl0, bl1);
                }
            }
            if (lane == 0) {
                mbar_arrive(smbase + MB_B + 32 + w1 * 8);
                if (accB) mbar_arrive(smbase + MB_B + 32 + w2 * 8);
                mbar_arrive(smbase + MB_B + 80 + ast * 8);
            }
            wq += accB ? 2 : 1;
            aq += 1;
        };

        // partials for one acc, then reduce+cell
        auto epilogue = [&](const float* acc, int l, const float* g0p,
                            float& cref, unsigned char* outimg, float* h1out,
                            bool fence_after) {
            {
                float* P = (float*)(smc + PT_B) + wid * 1056;
                const int r0 = lane >> 2;
                const int c0i = (lane & 3) << 1;
#pragma unroll
                for (int mf = 0; mf < 2; mf++) {
#pragma unroll
                    for (int nf = 0; nf < 4; nf++) {
                        const float* a = acc + (mf * 4 + nf) * 4;
                        const int rr = mf * 16 + r0;
                        const int cc = nf * 8 + c0i;
                        P[rr * 33 + cc]           = a[0];
                        P[rr * 33 + cc + 1]       = a[1];
                        P[(rr + 8) * 33 + cc]     = a[2];
                        P[(rr + 8) * 33 + cc + 1] = a[3];
                    }
                }
            }
            NB256();
            {
                float* BS = (float*)(smc + BS_B);
                float gi = BS[l * 32 + cu];
                float gf = BS[l * 32 + 8 + cu];
                float gg = BS[l * 32 + 16 + cu];
                float go = BS[l * 32 + 24 + cu];
                if (g0p) { gi += g0p[0]; gf += g0p[1]; gg += g0p[2]; go += g0p[3]; }
#pragma unroll
                for (int w = 0; w < 8; w++) {
                    const float* P = (float*)(smc + PT_B) + w * 1056;
                    gi += P[(0 * 8 + cu) * 33 + cb];
                    gf += P[(1 * 8 + cu) * 33 + cb];
                    gg += P[(2 * 8 + cu) * 33 + cb];
                    go += P[(3 * 8 + cu) * 33 + cb];
                }
                float si = 1.f / (1.f + __expf(-gi));
                float sf = 1.f / (1.f + __expf(-gf));
                float so = 1.f / (1.f + __expf(-go));
                float cN = sf * cref + si * tanhf(gg);
                float hN = so * tanhf(cN);
                cref = cN;
                const int u = r * 8 + cu;
                store_act(outimg, cb, u, hN);
                if (h1out) __stcg(&h1out[cb * H_ + u], hN);
            }
            if (fence_after) __threadfence();
            NB256();
        };

        // ---- prologue: h0(0) = cell0(G0(0) + Whh0 . h0init) ----
        {
            float g0r[4];
            const float* G0row = d_G0 + ((size_t)0 * 128 + r) * 1024;
            g0r[0] = __ldcg(&G0row[(0 * 8 + cu) * 32 + cb]);
            g0r[1] = __ldcg(&G0row[(1 * 8 + cu) * 32 + cb]);
            g0r[2] = __ldcg(&G0row[(2 * 8 + cu) * 32 + cb]);
            g0r[3] = __ldcg(&G0row[(3 * 8 + cu) * 32 + cb]);
#pragma unroll
            for (int i = 0; i < 32; i++) acc0[i] = 0.f;
            for (int c = 0; c < 4; c++) chunk(acc0, (float*)0);
            epilogue(acc0, 0, g0r, c0, d_h0img[0], (float*)0, true);
            if (tid == 0) {
                unsigned a = atomicAdd(&g_arrive, 1u) + 1u;
                if (a == (unsigned)NCTA * 2u) atomicExch(&g_release, 2u);
            }
        }

#pragma unroll 1
        for (int t = 0; t < T_; t++) {
            // prefetch G0(t+1) (clamped; value unused for t = T-1)
            const int tg = (t + 1 < T_) ? (t + 1) : (T_ - 1);
            float g0r[4];
            const float* G0row = d_G0 + ((size_t)tg * 128 + r) * 1024;
            g0r[0] = __ldcg(&G0row[(0 * 8 + cu) * 32 + cb]);
            g0r[1] = __ldcg(&G0row[(1 * 8 + cu) * 32 + cb]);
            g0r[2] = __ldcg(&G0row[(2 * 8 + cu) * 32 + cb]);
            g0r[3] = __ldcg(&G0row[(3 * 8 + cu) * 32 + cb]);

#pragma unroll
            for (int i = 0; i < 32; i++) { acc0[i] = 0.f; acc1[i] = 0.f; }

            // 4 single chunks: acc1 += Whh1 . h1(t-1)
            for (int c = 0; c < 4; c++) chunk(acc1, (float*)0);
            // 4 dual chunks: acc1 += Wih1 . h0(t); acc0 += Whh0 . h0(t)
            for (int c = 0; c < 4; c++) chunk(acc1, acc0);

            // cell1 -> h1(t), H1[t]
            epilogue(acc1, 1, (const float*)0, c1, d_h1img[t & 1],
                     d_H1 + (size_t)t * B_ * H_, false);
            // cell0 -> h0(t+1)
            epilogue(acc0, 0, g0r, c0, d_h0img[(t + 1) & 1], (float*)0, true);

            // publish gen t+3
            if (tid == 0) {
                unsigned a = atomicAdd(&g_arrive, 1u) + 1u;
                if (a == (unsigned)NCTA * (unsigned)(t + 3)) {
                    atomicExch(&g_release, (unsigned)(t + 3));
                }
            }
        }
    }
}

// ---------------------------------------------------------------------------
extern "C" void kernel_launch(void* const* d_in, const int* in_sizes, int n_in,
                              void* d_out, int out_size) {
    const float* x       = (const float*)d_in[0];
    const float* W_embed = (const float*)d_in[1];
    const float* b_embed = (const float*)d_in[2];
    const float* W_ih    = (const float*)d_in[3];
    const float* b_ih    = (const float*)d_in[4];
    const float* W_hh    = (const float*)d_in[5];
    const float* b_hh    = (const float*)d_in[6];
    const float* W_out   = (const float*)d_in[7];
    const float* b_out   = (const float*)d_in[8];
    const float* h0      = (const float*)d_in[9];
    float* out = (float*)d_out;

    cudaFuncSetAttribute(lstm_persistent,
                         cudaFuncAttributeMaxDynamicSharedMemorySize, SMEM_BYTES);

    m0_kernel<<<512, 128>>>(W_ih, W_embed, b_embed);
    prep_weights<<<dim3(128, 2), 256>>>(W_ih, W_hh);
    g0_kernel<<<dim3(128, T_), 256>>>(x);
    lstm_persistent<<<NCTA, NTHR, SMEM_BYTES>>>(b_ih, b_hh, h0);
    out_kernel<<<T_, 128>>>(W_out, b_out, out);
}

// round 16
// speedup vs baseline: 1.0140x; 1.0140x over previous
#include <cuda_runtime.h>
#include <cuda_bf16.h>
#include <math.h>
#include <stdint.h>

// Problem dims
#define B_   32
#define T_   512
#define IN_  128
#define H_   1024
#define OUT_ 128

// Persistent kernel config
#define NCTA 128
#define NTHR 288                // 8 consumer warps + 1 producer warp (2 active thr)

// SMEM layout (bytes)
//   W ring : 4 slots x 32768      [0, 131072)
//   A ring : 2 slots x 32768      [131072, 196608)
//   partials: 8 x 32x33 f32       [196608, 230400)
//   bias   : 64 f32               [230400, 230656)
//   mbars  : WF[4] WE[4] AF[2] AE[2]  [230656, 230752)
#define AR_B  131072
#define PT_B  196608
#define BS_B  230400
#define MB_B  230656
#define SMEM_BYTES 230752

typedef __nv_bfloat16 bf16;

// ---------------------------------------------------------------------------
// Device scratch
// ---------------------------------------------------------------------------
__device__ float d_M0  [4096 * 128];            // Wih0 @ W_emb^T
__device__ float d_bv0 [4096];                  // Wih0 @ b_emb
__device__ float d_G0  [(size_t)T_ * 128 * 32 * 32];   // [t][r][m][b] fp32
__device__ float d_H1  [(size_t)T_ * B_ * H_];  // layer-1 h, fp32
// Swizzled SMEM-image weight blocks: [(l*128+r)][chunk 0..7][hi 16K][lo 16K]
// l=0: chunks 0..3 = Whh0.  l=1: chunks 0..3 = Wih1, 4..7 = Whh1.
__device__ unsigned char d_Wimg[(size_t)2 * 128 * 8 * 32768];
// Swizzled act images: [parity][chunk 0..3][hi 16K][lo 16K]
__device__ unsigned char d_h0img[2][4 * 32768];
__device__ unsigned char d_h1img[2][4 * 32768];
__device__ unsigned g_arrive;
__device__ unsigned g_release;

// ---------------------------------------------------------------------------
// PTX helpers
// ---------------------------------------------------------------------------
#define NB256() asm volatile("bar.sync 1, 256;" ::: "memory")

__device__ __forceinline__ void bulk_ld(uint32_t dst, const void* src, uint32_t bytes, uint32_t mbar) {
    asm volatile("cp.async.bulk.shared::cta.global.mbarrier::complete_tx::bytes [%0], [%1], %2, [%3];"
                 :: "r"(dst), "l"(src), "r"(bytes), "r"(mbar) : "memory");
}
__device__ __forceinline__ void mbar_init(uint32_t mbar, uint32_t cnt) {
    asm volatile("mbarrier.init.shared.b64 [%0], %1;" :: "r"(mbar), "r"(cnt) : "memory");
}
__device__ __forceinline__ void mbar_expect(uint32_t mbar, uint32_t tx) {
    asm volatile("mbarrier.arrive.expect_tx.shared.b64 _, [%0], %1;" :: "r"(mbar), "r"(tx) : "memory");
}
__device__ __forceinline__ void mbar_arrive(uint32_t mbar) {
    asm volatile("mbarrier.arrive.shared.b64 _, [%0];" :: "r"(mbar) : "memory");
}
__device__ __forceinline__ void mbar_wait(uint32_t mbar, uint32_t ph) {
    asm volatile(
        "{\n\t.reg .pred P;\n\t"
        "WAIT_%=:\n\t"
        "mbarrier.try_wait.parity.shared.b64 P, [%0], %1, 0x989680;\n\t"
        "@P bra.uni DONE_%=;\n\t"
        "bra.uni WAIT_%=;\n\t"
        "DONE_%=:\n\t}"
        :: "r"(mbar), "r"(ph) : "memory");
}
__device__ __forceinline__ void ldsm_x4(uint32_t* r, uint32_t addr) {
    asm volatile("ldmatrix.sync.aligned.m8n8.x4.shared.b16 {%0,%1,%2,%3}, [%4];\n"
                 : "=r"(r[0]), "=r"(r[1]), "=r"(r[2]), "=r"(r[3]) : "r"(addr));
}
__device__ __forceinline__ void mma_bf16(float* c, const uint32_t* a, const uint32_t* b) {
    asm volatile("mma.sync.aligned.m16n8k16.row.col.f32.bf16.bf16.f32 "
                 "{%0,%1,%2,%3}, {%4,%5,%6,%7}, {%8,%9}, {%0,%1,%2,%3};\n"
                 : "+f"(c[0]), "+f"(c[1]), "+f"(c[2]), "+f"(c[3])
                 : "r"(a[0]), "r"(a[1]), "r"(a[2]), "r"(a[3]), "r"(b[0]), "r"(b[1]));
}
__device__ __forceinline__ unsigned ld_acq(const unsigned* p) {
    unsigned v;
    asm volatile("ld.acquire.gpu.global.u32 %0, [%1];" : "=r"(v) : "l"(p));
    return v;
}
// 24 mmas: 3-term bf16-split product of one 32x32 tile slice (one kk)
__device__ __forceinline__ void terms24(float* acc,
    const uint32_t* ah0, const uint32_t* ah1,
    const uint32_t* al0, const uint32_t* al1,
    const uint32_t* bh0, const uint32_t* bh1,
    const uint32_t* bl0, const uint32_t* bl1)
{
    mma_bf16(acc + 0,  ah0, bh0 + 0); mma_bf16(acc + 4,  ah0, bh0 + 2);
    mma_bf16(acc + 8,  ah0, bh1 + 0); mma_bf16(acc + 12, ah0, bh1 + 2);
    mma_bf16(acc + 16, ah1, bh0 + 0); mma_bf16(acc + 20, ah1, bh0 + 2);
    mma_bf16(acc + 24, ah1, bh1 + 0); mma_bf16(acc + 28, ah1, bh1 + 2);

    mma_bf16(acc + 0,  ah0, bl0 + 0); mma_bf16(acc + 4,  ah0, bl0 + 2);
    mma_bf16(acc + 8,  ah0, bl1 + 0); mma_bf16(acc + 12, ah0, bl1 + 2);
    mma_bf16(acc + 16, ah1, bl0 + 0); mma_bf16(acc + 20, ah1, bl0 + 2);
    mma_bf16(acc + 24, ah1, bl1 + 0); mma_bf16(acc + 28, ah1, bl1 + 2);

    mma_bf16(acc + 0,  al0, bh0 + 0); mma_bf16(acc + 4,  al0, bh0 + 2);
    mma_bf16(acc + 8,  al0, bh1 + 0); mma_bf16(acc + 12, al0, bh1 + 2);
    mma_bf16(acc + 16, al1, bh0 + 0); mma_bf16(acc + 20, al1, bh0 + 2);
    mma_bf16(acc + 24, al1, bh1 + 0); mma_bf16(acc + 28, al1, bh1 + 2);
}
// write one activation value into a swizzled chunk-blocked hi/lo image
__device__ __forceinline__ void store_act(unsigned char* img, int b, int u, float v) {
    bf16 hi = __float2bfloat16(v);
    bf16 lo = __float2bfloat16(v - __bfloat162float(hi));
    uint32_t x  = ((uint32_t)(u & 255)) * 2u;
    uint32_t sx = x ^ ((uint32_t)(b & 7) << 4);
    unsigned char* p = img + (((size_t)(u >> 8)) << 15) + (uint32_t)b * 512u + sx;
    unsigned short hb = __bfloat16_as_ushort(hi), lb = __bfloat16_as_ushort(lo);
    asm volatile("st.global.cg.u16 [%0], %1;" :: "l"(p), "h"(hb));
    asm volatile("st.global.cg.u16 [%0], %1;" :: "l"(p + 16384), "h"(lb));
}

// ---------------------------------------------------------------------------
// Full-block grid barrier (init only)
// ---------------------------------------------------------------------------
__device__ __forceinline__ void gridbar_full(unsigned gen) {
    __threadfence();
    __syncthreads();
    if (threadIdx.x == 0) {
        unsigned a = atomicAdd(&g_arrive, 1u) + 1u;
        if (a == (unsigned)NCTA * gen) {
            atomicExch(&g_release, gen);
        } else {
            while (*((volatile unsigned*)&g_release) < gen) __nanosleep(32);
        }
    }
    __syncthreads();
}

// ---------------------------------------------------------------------------
// M0 = Wih0 @ W_emb^T [4096 x 128], bvec0 = Wih0 @ b_emb.  Exact fp32.
// ---------------------------------------------------------------------------
__global__ void m0_kernel(const float* __restrict__ Wih,
                          const float* __restrict__ Wemb,
                          const float* __restrict__ bemb) {
    __shared__ float wih_s[8][1024];
    __shared__ float red[128];
    const int tid = threadIdx.x;
    const int j0  = blockIdx.x * 8;

    if (blockIdx.x == 0 && tid == 0) { g_arrive = 0u; g_release = 0u; }

    for (int i = tid; i < 8 * 1024; i += 128) {
        int jj = i >> 10, k = i & 1023;
        wih_s[jj][k] = Wih[(size_t)(j0 + jj) * 1024 + k];
    }
    __syncthreads();

    float acc[8];
#pragma unroll
    for (int jj = 0; jj < 8; jj++) acc[jj] = 0.f;
    float bp[8];
#pragma unroll
    for (int jj = 0; jj < 8; jj++) bp[jj] = 0.f;

    for (int k = 0; k < 1024; k++) {
        float we = Wemb[k * 128 + tid];
#pragma unroll
        for (int jj = 0; jj < 8; jj++) acc[jj] += wih_s[jj][k] * we;
    }
    for (int k = tid; k < 1024; k += 128) {
        float be = bemb[k];
#pragma unroll
        for (int jj = 0; jj < 8; jj++) bp[jj] += wih_s[jj][k] * be;
    }
#pragma unroll
    for (int jj = 0; jj < 8; jj++) {
        d_M0[(size_t)(j0 + jj) * 128 + tid] = acc[jj];
        __syncthreads();
        red[tid] = bp[jj];
        __syncthreads();
        for (int s = 64; s > 0; s >>= 1) {
            if (tid < s) red[tid] += red[tid + s];
            __syncthreads();
        }
        if (tid == 0) d_bv0[j0 + jj] = red[0];
    }
}

// ---------------------------------------------------------------------------
// G0[t][r][m][b] = x[b][t][:] . M0[j(r,m)][:] + bvec0[j].  grid (128, 512).
// ---------------------------------------------------------------------------
__global__ void g0_kernel(const float* __restrict__ x) {
    __shared__ float xs[32][129];
    const int r = blockIdx.x, t = blockIdx.y;
    const int tid = threadIdx.x;

    for (int i = tid; i < 32 * 128; i += 256) {
        int b = i >> 7, k = i & 127;
        xs[b][k] = x[((size_t)b * T_ + t) * IN_ + k];
    }
    __syncthreads();

    const int m  = tid >> 3;
    const int bq = (tid & 7) * 4;
    const int j  = ((m >> 3) << 10) + (r << 3) + (m & 7);
    const float* M0r = d_M0 + (size_t)j * 128;

    float acc[4];
    const float bv = d_bv0[j];
#pragma unroll
    for (int i = 0; i < 4; i++) acc[i] = bv;

#pragma unroll 4
    for (int k = 0; k < 128; k++) {
        float w = M0r[k];
#pragma unroll
        for (int i = 0; i < 4; i++) acc[i] += w * xs[bq + i][k];
    }
    float4 v = make_float4(acc[0], acc[1], acc[2], acc[3]);
    *(float4*)(d_G0 + (((size_t)t * 128 + r) * 32 + m) * 32 + bq) = v;
}

// ---------------------------------------------------------------------------
// Weight prep (unchanged layout)
// ---------------------------------------------------------------------------
__global__ void prep_weights(const float* __restrict__ Wih,
                             const float* __restrict__ Whh) {
    const int r = blockIdx.x, l = blockIdx.y;
    unsigned char* base = d_Wimg + ((size_t)(l * 128 + r) << 18);

    for (int g = threadIdx.x; g < 8192; g += 256) {
        int c  = g >> 10;
        int m  = (g >> 5) & 31;
        int gk = g & 31;
        if (l == 0 && c >= 4) continue;
        int j = ((m >> 3) << 10) + (r << 3) + (m & 7);
        const float* src;
        if (l == 0)      src = Whh + (size_t)j * 1024 + c * 256 + gk * 8;
        else if (c < 4)  src = Wih + (size_t)(4096 + j) * 1024 + c * 256 + gk * 8;
        else             src = Whh + (size_t)(4096 + j) * 1024 + (c - 4) * 256 + gk * 8;

        float f[8];
        float4 v0 = ((const float4*)src)[0];
        float4 v1 = ((const float4*)src)[1];
        f[0]=v0.x; f[1]=v0.y; f[2]=v0.z; f[3]=v0.w;
        f[4]=v1.x; f[5]=v1.y; f[6]=v1.z; f[7]=v1.w;
        unsigned short hb[8], lb[8];
#pragma unroll
        for (int i = 0; i < 8; i++) {
            bf16 hi = __float2bfloat16(f[i]);
            bf16 lo = __float2bfloat16(f[i] - __bfloat162float(hi));
            hb[i] = __bfloat16_as_ushort(hi);
            lb[i] = __bfloat16_as_ushort(lo);
        }
        uint4 hv, lv;
        hv.x = (uint32_t)hb[0] | ((uint32_t)hb[1] << 16);
        hv.y = (uint32_t)hb[2] | ((uint32_t)hb[3] << 16);
        hv.z = (uint32_t)hb[4] | ((uint32_t)hb[5] << 16);
        hv.w = (uint32_t)hb[6] | ((uint32_t)hb[7] << 16);
        lv.x = (uint32_t)lb[0] | ((uint32_t)lb[1] << 16);
        lv.y = (uint32_t)lb[2] | ((uint32_t)lb[3] << 16);
        lv.z = (uint32_t)lb[4] | ((uint32_t)lb[5] << 16);
        lv.w = (uint32_t)lb[6] | ((uint32_t)lb[7] << 16);
        uint32_t off = (uint32_t)m * 512u + (((uint32_t)gk << 4) ^ ((uint32_t)(m & 7) << 4));
        *(uint4*)(base + ((size_t)c << 15) + off)         = hv;
        *(uint4*)(base + ((size_t)c << 15) + 16384 + off) = lv;
    }
}

// ---------------------------------------------------------------------------
// Output kernel: out[b][t][o] = H1[t][b][:] . W_out[o][:] + b_out
// ---------------------------------------------------------------------------
__global__ void out_kernel(const float* __restrict__ Wout,
                           const float* __restrict__ bout,
                           float* __restrict__ out) {
    __shared__ float hs[B_][128];
    const int t   = blockIdx.x;
    const int tid = threadIdx.x;

    float acc[B_];
    const float bv = bout[tid];
#pragma unroll
    for (int b = 0; b < B_; b++) acc[b] = bv;

    for (int kc = 0; kc < H_; kc += 128) {
        __syncthreads();
        for (int i = tid; i < B_ * 128; i += 128) {
            int b = i >> 7, k = i & 127;
            hs[b][k] = d_H1[((size_t)t * B_ + b) * H_ + kc + k];
        }
        __syncthreads();
        const float4* wr = (const float4*)(Wout + tid * H_ + kc);
#pragma unroll 4
        for (int k4 = 0; k4 < 32; k4++) {
            float4 w = wr[k4];
            int k = k4 * 4;
#pragma unroll
            for (int b = 0; b < B_; b++) {
                acc[b] += hs[b][k] * w.x + hs[b][k + 1] * w.y +
                          hs[b][k + 2] * w.z + hs[b][k + 3] * w.w;
            }
        }
    }
#pragma unroll
    for (int b = 0; b < B_; b++) out[((size_t)b * T_ + t) * OUT_ + tid] = acc[b];
}

// ---------------------------------------------------------------------------
// Persistent LSTM kernel — split W/act rings with DECOUPLED producers:
//   tid 256: W-producer, free-running (no barrier dependency, W-ring only)
//   tid 257: act-producer, gated on g_release per step (act-ring only)
//   Consumers: FIFO on both rings, merged-GEMM schedule (R14/R15).
// ---------------------------------------------------------------------------
__global__ void __launch_bounds__(NTHR, 1) lstm_persistent(
    const float* __restrict__ bih, const float* __restrict__ bhh,
    const float* __restrict__ h0)
{
    extern __shared__ char smc[];
    const int tid = threadIdx.x;
    const int r   = blockIdx.x;
    const uint32_t smbase = (uint32_t)__cvta_generic_to_shared(smc);

    if (tid == 0) {
#pragma unroll
        for (int s = 0; s < 4; s++) {
            mbar_init(smbase + MB_B + s * 8, 1);            // W full (tx)
            mbar_init(smbase + MB_B + 32 + s * 8, 8);       // W empty (8 warps)
        }
#pragma unroll
        for (int s = 0; s < 2; s++) {
            mbar_init(smbase + MB_B + 64 + s * 8, 1);       // A full (tx)
            mbar_init(smbase + MB_B + 80 + s * 8, 8);       // A empty (8 warps)
        }
    }
    if (tid < 64) {
        int l = tid >> 5, n = tid & 31;
        int j = ((n >> 3) << 10) + (r << 3) + (n & 7);
        ((float*)(smc + BS_B))[tid] = bih[l * 4 * H_ + j] + bhh[l * 4 * H_ + j];
    }
    float c0 = 0.f, c1 = 0.f;           // register-resident cell state
    if (tid < 256) {
        const int b = tid >> 3, uu = tid & 7;
        const int u = r * 8 + uu;
        const int base = b * (4 * H_);
        float h_l0 = h0[base + 0 * 2 * H_ + u];
        c0         = h0[base + 0 * 2 * H_ + H_ + u];
        float h_l1 = h0[base + 1 * 2 * H_ + u];
        c1         = h0[base + 1 * 2 * H_ + H_ + u];
        store_act(d_h0img[1], b, u, h_l0);   // h0(-1) at parity 1
        store_act(d_h1img[1], b, u, h_l1);   // h1(-1) at parity 1
    }
    gridbar_full(1u);                   // gen 1: init images published

    const unsigned char* wbase0 = d_Wimg + ((size_t)(0 * 128 + r) << 18);
    const unsigned char* wbase1 = d_Wimg + ((size_t)(1 * 128 + r) << 18);

    if (tid == 256) {
        // --------------- W PRODUCER: free-running, no barrier waits ----------
        int wq = 0, wiq = 0, wepar = 0;
        auto issueW = [&](const unsigned char* src) {
            const int st = wq & 3;
            if (wiq >= 4) {
                mbar_wait(smbase + MB_B + 32 + st * 8, (uint32_t)((wepar >> st) & 1));
                wepar ^= (1 << st);
            }
            wiq++;
            uint32_t mb = smbase + MB_B + st * 8;
            mbar_expect(mb, 32768u);
            bulk_ld(smbase + (uint32_t)st * 32768u, src, 32768u, mb);
            wq++;
        };
        for (int c = 0; c < 4; c++) issueW(wbase0 + ((size_t)c << 15));
#pragma unroll 1
        for (int t = 0; t < T_; t++) {
            for (int c = 0; c < 4; c++)
                issueW(wbase1 + ((size_t)(4 + c) << 15));
            for (int c = 0; c < 4; c++) {
                issueW(wbase1 + ((size_t)c << 15));
                issueW(wbase0 + ((size_t)c << 15));
            }
        }
    } else if (tid == 257) {
        // --------------- ACT PRODUCER: gated on g_release per step ----------
        int aq = 0, aiq = 0, aepar = 0;
        auto issueA = [&](const unsigned char* src) {
            const int st = aq & 1;
            if (aiq >= 2) {
                mbar_wait(smbase + MB_B + 80 + st * 8, (uint32_t)((aepar >> st) & 1));
                aepar ^= (1 << st);
            }
            aiq++;
            uint32_t mb = smbase + MB_B + 64 + st * 8;
            mbar_expect(mb, 32768u);
            bulk_ld(smbase + AR_B + (uint32_t)st * 32768u, src, 32768u, mb);
            aq++;
        };
        // prologue: Whh0 x h0init (h0img[1])
        for (int c = 0; c < 4; c++) issueA(d_h0img[1] + ((size_t)c << 15));
#pragma unroll 1
        for (int t = 0; t < T_; t++) {
            while (ld_acq(&g_release) < (unsigned)(t + 2)) __nanosleep(32);
            for (int c = 0; c < 4; c++)
                issueA(d_h1img[(t + 1) & 1] + ((size_t)c << 15));
            for (int c = 0; c < 4; c++)
                issueA(d_h0img[t & 1] + ((size_t)c << 15));
        }
    } else if (tid < 256) {
        // ------------------------- CONSUMERS ---------------------------------
        const int wid  = tid >> 5;
        const int lane = tid & 31;
        const int jj = lane & 7, s8 = lane >> 3;
        const int cb = (tid >> 3) & 31;
        const int cu = tid & 7;

        const uint32_t rA   = (uint32_t)(((s8 & 1) << 3) + jj);
        const uint32_t dA   = (uint32_t)((s8 >> 1) << 4);
        const uint32_t rB   = (uint32_t)(((s8 >> 1) << 3) + jj);
        const uint32_t dB   = (uint32_t)((s8 & 1) << 4);
        const uint32_t xorJ = (uint32_t)(jj << 4);

        int wq = 0, wparm = 0, aq = 0, aparm = 0;

        float acc0[32], acc1[32];

        // one chunk: act slot + 1 or 2 W slots (shared act ldsm)
        auto chunk = [&](float* accA, float* accB) {
            const int ast = aq & 1;
            mbar_wait(smbase + MB_B + 64 + ast * 8, (uint32_t)((aparm >> ast) & 1));
            aparm ^= (1 << ast);
            const uint32_t bb = smbase + AR_B + (uint32_t)ast * 32768u + rB * 512;
            const int w1 = wq & 3;
            mbar_wait(smbase + MB_B + w1 * 8, (uint32_t)((wparm >> w1) & 1));
            wparm ^= (1 << w1);
            const uint32_t a1 = smbase + (uint32_t)w1 * 32768u + rA * 512;
            int w2 = -1;
            uint32_t a2 = 0;
            if (accB) {
                w2 = (wq + 1) & 3;
                mbar_wait(smbase + MB_B + w2 * 8, (uint32_t)((wparm >> w2) & 1));
                wparm ^= (1 << w2);
                a2 = smbase + (uint32_t)w2 * 32768u + rA * 512;
            }
#pragma unroll
            for (int kx = 0; kx < 2; kx++) {
                const int kk = (wid << 1) + kx;
                const uint32_t offA = (((uint32_t)(kk << 5)) | dA) ^ xorJ;
                const uint32_t offB = (((uint32_t)(kk << 5)) | dB) ^ xorJ;
                uint32_t bh0[4], bh1[4], bl0[4], bl1[4];
                ldsm_x4(bh0, bb + offB);
                ldsm_x4(bh1, bb + 8192 + offB);
                ldsm_x4(bl0, bb + 16384 + offB);
                ldsm_x4(bl1, bb + 16384 + 8192 + offB);
                {
                    uint32_t ah0[4], ah1[4], al0[4], al1[4];
                    ldsm_x4(ah0, a1 + offA);
                    ldsm_x4(ah1, a1 + 8192 + offA);
                    ldsm_x4(al0, a1 + 16384 + offA);
                    ldsm_x4(al1, a1 + 16384 + 8192 + offA);
                    terms24(accA, ah0, ah1, al0, al1, bh0, bh1, bl0, bl1);
                }
                if (accB) {
                    uint32_t ah0[4], ah1[4], al0[4], al1[4];
                    ldsm_x4(ah0, a2 + offA);
                    ldsm_x4(ah1, a2 + 8192 + offA);
                    ldsm_x4(al0, a2 + 16384 + offA);
                    ldsm_x4(al1, a2 + 16384 + 8192 + offA);
                    terms24(accB, ah0, ah1, al0, al1, bh0, bh1, bl0, bl1);
                }
            }
            if (lane == 0) {
                mbar_arrive(smbase + MB_B + 32 + w1 * 8);
                if (accB) mbar_arrive(smbase + MB_B + 32 + w2 * 8);
                mbar_arrive(smbase + MB_B + 80 + ast * 8);
            }
            wq += accB ? 2 : 1;
            aq += 1;
        };

        // partials for one acc, then reduce+cell
        auto epilogue = [&](const float* acc, int l, const float* g0p,
                            float& cref, unsigned char* outimg, float* h1out,
                            bool fence_after) {
            {
                float* P = (float*)(smc + PT_B) + wid * 1056;
                const int r0 = lane >> 2;
                const int c0i = (lane & 3) << 1;
#pragma unroll
                for (int mf = 0; mf < 2; mf++) {
#pragma unroll
                    for (int nf = 0; nf < 4; nf++) {
                        const float* a = acc + (mf * 4 + nf) * 4;
                        const int rr = mf * 16 + r0;
                        const int cc = nf * 8 + c0i;
                        P[rr * 33 + cc]           = a[0];
                        P[rr * 33 + cc + 1]       = a[1];
                        P[(rr + 8) * 33 + cc]     = a[2];
                        P[(rr + 8) * 33 + cc + 1] = a[3];
                    }
                }
            }
            NB256();
            {
                float* BS = (float*)(smc + BS_B);
                float gi = BS[l * 32 + cu];
                float gf = BS[l * 32 + 8 + cu];
                float gg = BS[l * 32 + 16 + cu];
                float go = BS[l * 32 + 24 + cu];
                if (g0p) { gi += g0p[0]; gf += g0p[1]; gg += g0p[2]; go += g0p[3]; }
#pragma unroll
                for (int w = 0; w < 8; w++) {
                    const float* P = (float*)(smc + PT_B) + w * 1056;
                    gi += P[(0 * 8 + cu) * 33 + cb];
                    gf += P[(1 * 8 + cu) * 33 + cb];
                    gg += P[(2 * 8 + cu) * 33 + cb];
                    go += P[(3 * 8 + cu) * 33 + cb];
                }
                float si = 1.f / (1.f + __expf(-gi));
                float sf = 1.f / (1.f + __expf(-gf));
                float so = 1.f / (1.f + __expf(-go));
                float cN = sf * cref + si * tanhf(gg);
                float hN = so * tanhf(cN);
                cref = cN;
                const int u = r * 8 + cu;
                store_act(outimg, cb, u, hN);
                if (h1out) __stcg(&h1out[cb * H_ + u], hN);
            }
            if (fence_after) __threadfence();
            NB256();
        };

        // ---- prologue: h0(0) = cell0(G0(0) + Whh0 . h0init) ----
        {
            float g0r[4];
            const float* G0row = d_G0 + ((size_t)0 * 128 + r) * 1024;
            g0r[0] = __ldcg(&G0row[(0 * 8 + cu) * 32 + cb]);
            g0r[1] = __ldcg(&G0row[(1 * 8 + cu) * 32 + cb]);
            g0r[2] = __ldcg(&G0row[(2 * 8 + cu) * 32 + cb]);
            g0r[3] = __ldcg(&G0row[(3 * 8 + cu) * 32 + cb]);
#pragma unroll
            for (int i = 0; i < 32; i++) acc0[i] = 0.f;
            for (int c = 0; c < 4; c++) chunk(acc0, (float*)0);
            epilogue(acc0, 0, g0r, c0, d_h0img[0], (float*)0, true);
            if (tid == 0) {
                unsigned a = atomicAdd(&g_arrive, 1u) + 1u;
                if (a == (unsigned)NCTA * 2u) atomicExch(&g_release, 2u);
            }
        }

#pragma unroll 1
        for (int t = 0; t < T_; t++) {
            // prefetch G0(t+1) (clamped; value unused for t = T-1)
            const int tg = (t + 1 < T_) ? (t + 1) : (T_ - 1);
            float g0r[4];
            const float* G0row = d_G0 + ((size_t)tg * 128 + r) * 1024;
            g0r[0] = __ldcg(&G0row[(0 * 8 + cu) * 32 + cb]);
            g0r[1] = __ldcg(&G0row[(1 * 8 + cu) * 32 + cb]);
            g0r[2] = __ldcg(&G0row[(2 * 8 + cu) * 32 + cb]);
            g0r[3] = __ldcg(&G0row[(3 * 8 + cu) * 32 + cb]);

#pragma unroll
            for (int i = 0; i < 32; i++) { acc0[i] = 0.f; acc1[i] = 0.f; }

            // 4 single chunks: acc1 += Whh1 . h1(t-1)
            for (int c = 0; c < 4; c++) chunk(acc1, (float*)0);
            // 4 dual chunks: acc1 += Wih1 . h0(t); acc0 += Whh0 . h0(t)
            for (int c = 0; c < 4; c++) chunk(acc1, acc0);

            // cell1 -> h1(t), H1[t]
            epilogue(acc1, 1, (const float*)0, c1, d_h1img[t & 1],
                     d_H1 + (size_t)t * B_ * H_, false);
            // cell0 -> h0(t+1)
            epilogue(acc0, 0, g0r, c0, d_h0img[(t + 1) & 1], (float*)0, true);

            // publish gen t+3
            if (tid == 0) {
                unsigned a = atomicAdd(&g_arrive, 1u) + 1u;
                if (a == (unsigned)NCTA * (unsigned)(t + 3)) {
                    atomicExch(&g_release, (unsigned)(t + 3));
                }
            }
        }
    }
}

// ---------------------------------------------------------------------------
extern "C" void kernel_launch(void* const* d_in, const int* in_sizes, int n_in,
                              void* d_out, int out_size) {
    const float* x       = (const float*)d_in[0];
    const float* W_embed = (const float*)d_in[1];
    const float* b_embed = (const float*)d_in[2];
    const float* W_ih    = (const float*)d_in[3];
    const float* b_ih    = (const float*)d_in[4];
    const float* W_hh    = (const float*)d_in[5];
    const float* b_hh    = (const float*)d_in[6];
    const float* W_out   = (const float*)d_in[7];
    const float* b_out   = (const float*)d_in[8];
    const float* h0      = (const float*)d_in[9];
    float* out = (float*)d_out;

    cudaFuncSetAttribute(lstm_persistent,
                         cudaFuncAttributeMaxDynamicSharedMemorySize, SMEM_BYTES);

    m0_kernel<<<512, 128>>>(W_ih, W_embed, b_embed);
    prep_weights<<<dim3(128, 2), 256>>>(W_ih, W_hh);
    g0_kernel<<<dim3(128, T_), 256>>>(x);
    lstm_persistent<<<NCTA, NTHR, SMEM_BYTES>>>(b_ih, b_hh, h0);
    out_kernel<<<T_, 128>>>(W_out, b_out, out);
}